// round 4
// baseline (speedup 1.0000x reference)
#include <cuda_runtime.h>

// Problem dims
#define NT 4
#define NB 8
#define NC1 64
#define NC2 128
#define HH 128
#define WW 128
#define HW 16384              // HH*WW
#define NIMG 32               // NT*NB
#define SP_PER_T 8388608      // NB*NC1*HW
#define NSPIKES 33554432      // NT*SP_PER_T
#define NY 67108864           // NIMG*NC2*HW
#define NELEM_PER_CH 524288   // NIMG*HW
#define NW 73728              // NC2*NC1*9

// Conv tiling
#define CC 8                  // input-channel chunk in smem
#define SROW 36               // padded row stride (34 valid cols)
#define SCH (18*SROW)         // 648 floats per channel slab (18 rows)
#define CHUNK_ELEMS (CC*18*34) // 4896 valid elements per chunk
#define NLD 20                // ceil(4896/256)
#define WSM_FLOATS (NC1*9*32) // 18432
#define SMEM_FLOATS (WSM_FLOATS + 2*CC*SCH)
#define SMEM_BYTES (SMEM_FLOATS*4)  // 115200 B

// Scratch (device globals are allowed; runtime allocation is not)
__device__ float g_spikes[NSPIKES];
__device__ float g_y[NY];
__device__ float g_wt[NW];
__device__ float g_psum[NC2*NIMG];
__device__ float g_psumsq[NC2*NIMG];
__device__ float g_scale[NC2];
__device__ float g_shift[NC2];

// ---------- packed fp32x2 helpers (Blackwell FFMA2) ----------
__device__ __forceinline__ unsigned long long fma2(unsigned long long a,
                                                   unsigned long long b,
                                                   unsigned long long c) {
    unsigned long long d;
    asm("fma.rn.f32x2 %0, %1, %2, %3;" : "=l"(d) : "l"(a), "l"(b), "l"(c));
    return d;
}
__device__ __forceinline__ unsigned long long pack2(float x) {
    unsigned long long d;
    asm("mov.b64 %0, {%1, %2};" : "=l"(d) : "f"(x), "f"(x));
    return d;
}

// ---------- K1: LIF recurrence (matches jax scan + round-half-even) ----------
__global__ void lif_kernel(const float* __restrict__ x) {
    int i = blockIdx.x * 256 + threadIdx.x;
    float mem = 0.f, s = 0.f;
#pragma unroll
    for (int t = 0; t < NT; t++) {
        mem = (mem - 0.5f * s) * 0.25f + x[(size_t)t * SP_PER_T + i];
        s = rintf(fminf(fmaxf(mem, 0.f), 1.f));  // round-half-even == jnp.round
        g_spikes[(size_t)t * SP_PER_T + i] = s;
    }
}

// ---------- K0: weight transpose [o][c][k] -> [c*9+k][o] for coalesced smem fill ----------
__global__ void wtrans_kernel(const float* __restrict__ w) {
    int i = blockIdx.x * 256 + threadIdx.x;
    if (i < NW) {
        int k = i % 9;
        int c = (i / 9) % NC1;
        int o = i / (NC1 * 9);
        g_wt[(c * 9 + k) * NC2 + o] = w[i];
    }
}

// ---------- K2: direct 3x3 conv, f32x2-packed channels ----------
// grid: (32 tiles, 32 images, 4 channel groups), 256 threads.
// Thread: 8 contiguous x-positions x 8 output channels (4 f32x2 channel pairs).
__global__ void __launch_bounds__(256, 1) conv_kernel() {
    extern __shared__ float smem[];
    float* wsm = smem;  // [c*9+k][32] for this block's 32 output channels
    float* sbufA = smem + WSM_FLOATS;
    float* sbufB = sbufA + CC * SCH;

    const int n   = blockIdx.y;
    const int tx0 = (blockIdx.x & 3) * 32;
    const int ty0 = (blockIdx.x >> 2) * 16;
    const int o0  = blockIdx.z * 32;
    const int tid = threadIdx.x;
    const int slot = tid & 63;
    const int cg   = tid >> 6;          // uniform per warp -> LDS broadcast for weights
    const int sx   = (slot & 3) * 8;
    const int sy   = slot >> 2;

    // weights: coalesced global read, conflict-free smem write (index == linear i)
    for (int i = tid; i < WSM_FLOATS; i += 256) {
        int ol = i & 31;
        int ck = i >> 5;
        wsm[i] = g_wt[ck * NC2 + o0 + ol];
    }

    const float* simg = g_spikes + (size_t)n * (NC1 * HW);

    float v[NLD];  // register staging for the next chunk (overlaps compute)

    auto ldg_chunk = [&](int ckk) {
        int cb = ckk * CC;
#pragma unroll
        for (int j = 0; j < NLD; ++j) {
            int e = tid + j * 256;
            float val = 0.f;
            if (e < CHUNK_ELEMS) {
                int c  = e / 612;          // 612 = 18*34
                int r  = e - c * 612;
                int ly = r / 34;
                int lx = r - ly * 34;
                int gy = ty0 - 1 + ly;
                int gx = tx0 - 1 + lx;
                if ((unsigned)gy < HH && (unsigned)gx < WW)
                    val = simg[(cb + c) * HW + gy * WW + gx];
            }
            v[j] = val;
        }
    };
    auto sts_chunk = [&](float* buf) {
#pragma unroll
        for (int j = 0; j < NLD; ++j) {
            int e = tid + j * 256;
            if (e < CHUNK_ELEMS) {
                int c  = e / 612;
                int r  = e - c * 612;
                int ly = r / 34;
                int lx = r - ly * 34;
                buf[c * SCH + ly * SROW + lx] = v[j];
            }
        }
    };

    unsigned long long acc[4][8];
#pragma unroll
    for (int p = 0; p < 4; p++)
#pragma unroll
        for (int xx = 0; xx < 8; xx++) acc[p][xx] = 0ULL;

    ldg_chunk(0);
    sts_chunk(sbufA);
    ldg_chunk(1);
    __syncthreads();

    for (int ck = 0; ck < NC1 / CC; ++ck) {
        const float* cur = (ck & 1) ? sbufB : sbufA;
#pragma unroll 1
        for (int c = 0; c < CC; ++c) {
            const int wc = (ck * CC + c) * 9;
            const float* srow = cur + c * SCH;
#pragma unroll
            for (int ky = 0; ky < 3; ++ky) {
                const float* sp = srow + (sy + ky) * SROW + sx;  // 16B aligned
                float4 a  = *(const float4*)(sp);
                float4 b  = *(const float4*)(sp + 4);
                float2 c2 = *(const float2*)(sp + 8);
                unsigned long long sd[10];
                sd[0] = pack2(a.x);  sd[1] = pack2(a.y);
                sd[2] = pack2(a.z);  sd[3] = pack2(a.w);
                sd[4] = pack2(b.x);  sd[5] = pack2(b.y);
                sd[6] = pack2(b.z);  sd[7] = pack2(b.w);
                sd[8] = pack2(c2.x); sd[9] = pack2(c2.y);
#pragma unroll
                for (int kx = 0; kx < 3; ++kx) {
                    const float* wp = wsm + (wc + ky * 3 + kx) * 32 + cg * 8;
                    unsigned long long w0 = *(const unsigned long long*)(wp + 0);
                    unsigned long long w1 = *(const unsigned long long*)(wp + 2);
                    unsigned long long w2 = *(const unsigned long long*)(wp + 4);
                    unsigned long long w3 = *(const unsigned long long*)(wp + 6);
#pragma unroll
                    for (int xx = 0; xx < 8; ++xx) {
                        acc[0][xx] = fma2(w0, sd[xx + kx], acc[0][xx]);
                        acc[1][xx] = fma2(w1, sd[xx + kx], acc[1][xx]);
                        acc[2][xx] = fma2(w2, sd[xx + kx], acc[2][xx]);
                        acc[3][xx] = fma2(w3, sd[xx + kx], acc[3][xx]);
                    }
                }
            }
        }
        if (ck < NC1 / CC - 1) sts_chunk((ck & 1) ? sbufA : sbufB);
        __syncthreads();
        if (ck < NC1 / CC - 2) ldg_chunk(ck + 2);
    }

    // epilogue: 16 STG.128
    const int gy = ty0 + sy;
    const int gx = tx0 + sx;
#pragma unroll
    for (int p = 0; p < 4; ++p) {
        float lo[8], hi[8];
#pragma unroll
        for (int xx = 0; xx < 8; ++xx) {
            float2 f = *(float2*)&acc[p][xx];
            lo[xx] = f.x;
            hi[xx] = f.y;
        }
        int o = o0 + cg * 8 + 2 * p;
        float* y0 = g_y + ((size_t)n * NC2 + o) * HW + gy * WW + gx;
        *(float4*)(y0)     = make_float4(lo[0], lo[1], lo[2], lo[3]);
        *(float4*)(y0 + 4) = make_float4(lo[4], lo[5], lo[6], lo[7]);
        float* y1 = y0 + HW;
        *(float4*)(y1)     = make_float4(hi[0], hi[1], hi[2], hi[3]);
        *(float4*)(y1 + 4) = make_float4(hi[4], hi[5], hi[6], hi[7]);
    }
}

// ---------- K3a: deterministic per-(channel,image) partial sums ----------
__global__ void stats_partial() {
    const int c = blockIdx.x;
    const int n = blockIdx.y;
    const float* p = g_y + ((size_t)n * NC2 + c) * HW;
    float s = 0.f, s2 = 0.f;
    for (int i = threadIdx.x; i < HW; i += 256) {
        float val = p[i];
        s += val;
        s2 += val * val;
    }
    __shared__ float rs[256], rs2[256];
    rs[threadIdx.x] = s;
    rs2[threadIdx.x] = s2;
    __syncthreads();
    for (int st = 128; st > 0; st >>= 1) {
        if (threadIdx.x < st) {
            rs[threadIdx.x] += rs[threadIdx.x + st];
            rs2[threadIdx.x] += rs2[threadIdx.x + st];
        }
        __syncthreads();
    }
    if (threadIdx.x == 0) {
        g_psum[c * NIMG + n] = rs[0];
        g_psumsq[c * NIMG + n] = rs2[0];
    }
}

// ---------- K3b: finalize BN scale/shift ----------
__global__ void stats_final(const float* __restrict__ gamma,
                            const float* __restrict__ beta) {
    int c = threadIdx.x;
    float s = 0.f, s2 = 0.f;
    for (int n = 0; n < NIMG; n++) {
        s += g_psum[c * NIMG + n];
        s2 += g_psumsq[c * NIMG + n];
    }
    const float inv = 1.f / (float)NELEM_PER_CH;
    float mean = s * inv;
    float var = fmaxf(s2 * inv - mean * mean, 0.f);
    float r = rsqrtf(var + 1e-5f);
    float sc = gamma[c] * r;
    g_scale[c] = sc;
    g_shift[c] = beta[c] - mean * sc;
}

// ---------- K4: apply BN ----------
__global__ void bn_apply(float* __restrict__ out) {
    size_t i = (size_t)blockIdx.x * 256 + threadIdx.x;  // float4 index
    const float4 vy = ((const float4*)g_y)[i];
    int c = (int)((i >> 12) & 127);  // (i*4 / HW) % NC2
    float sc = g_scale[c], sh = g_shift[c];
    float4 o;
    o.x = fmaf(vy.x, sc, sh);
    o.y = fmaf(vy.y, sc, sh);
    o.z = fmaf(vy.z, sc, sh);
    o.w = fmaf(vy.w, sc, sh);
    ((float4*)out)[i] = o;
}

extern "C" void kernel_launch(void* const* d_in, const int* in_sizes, int n_in,
                              void* d_out, int out_size) {
    const float* x     = (const float*)d_in[0];
    const float* w     = (const float*)d_in[1];
    const float* gamma = (const float*)d_in[2];
    const float* beta  = (const float*)d_in[3];
    float* out = (float*)d_out;

    cudaFuncSetAttribute(conv_kernel, cudaFuncAttributeMaxDynamicSharedMemorySize,
                         SMEM_BYTES);

    lif_kernel<<<SP_PER_T / 256, 256>>>(x);
    wtrans_kernel<<<(NW + 255) / 256, 256>>>(w);
    conv_kernel<<<dim3(32, NIMG, 4), 256, SMEM_BYTES>>>();
    stats_partial<<<dim3(NC2, NIMG), 256>>>();
    stats_final<<<1, NC2>>>(gamma, beta);
    bn_apply<<<NY / 4 / 256, 256>>>(out);
}

// round 9
// speedup vs baseline: 2.4769x; 2.4769x over previous
#include <cuda_runtime.h>
#include <cuda_bf16.h>
#include <cstdint>

// ---------------- problem dims ----------------
#define NT 4
#define NB 8
#define NC1 64
#define NC2 128
#define HH 128
#define WW 128
#define HW 16384
#define NIMG 32
#define NSPIKES 33554432       // NIMG*NC1*HW
#define NY 67108864            // NIMG*NC2*HW
#define NELEM_PER_CH 524288
#define NW 73728

// ---------------- conv (mma.sync) config ----------------
#define STAGE 65536            // A(32K) + Bhi(16K) + Blo(16K)
#define OFF_BHI 32768
#define OFF_BLO 49152
#define SMEM_TOTAL (2*STAGE)   // 131072

// ---------------- device scratch ----------------
__device__ __nv_bfloat16 g_spikes[NSPIKES];   // [n][y][x][c]  channel-last
__device__ float g_y[NY];                     // [n][o][y][x]
__device__ __nv_bfloat16 g_whi[9*NC2*NC1];    // [kk][o][c]
__device__ __nv_bfloat16 g_wlo[9*NC2*NC1];
__device__ float g_psum[NC2*NIMG];
__device__ float g_psumsq[NC2*NIMG];
__device__ float g_scale[NC2];
__device__ float g_shift[NC2];

// ---------------- helpers ----------------
__device__ __forceinline__ uint32_t smem_u32(const void* p) {
    uint32_t a;
    asm("{ .reg .u64 t; cvta.to.shared.u64 t, %1; cvt.u32.u64 %0, t; }"
        : "=r"(a) : "l"(p));
    return a;
}

__device__ __forceinline__ void mma_bf16(float* d, const uint32_t* a,
                                         const uint32_t* b) {
    asm volatile(
        "mma.sync.aligned.m16n8k16.row.col.f32.bf16.bf16.f32 "
        "{%0,%1,%2,%3}, {%4,%5,%6,%7}, {%8,%9}, {%0,%1,%2,%3};"
        : "+f"(d[0]), "+f"(d[1]), "+f"(d[2]), "+f"(d[3])
        : "r"(a[0]), "r"(a[1]), "r"(a[2]), "r"(a[3]), "r"(b[0]), "r"(b[1]));
}

// ---------------- K1: LIF -> bf16 spikes, channel-last ----------------
// grid (8 b, 128 y, 4 cgroups), 256 threads.
__global__ void lif_kernel(const float* __restrict__ x) {
    __shared__ __nv_bfloat16 sbuf[128][24];   // 48B rows -> 16B-aligned uint4 reads
    const int b = blockIdx.x, y = blockIdx.y, cg = blockIdx.z;
    const int tid = threadIdx.x;
    const int c0 = cg * 16;
    const int wo = tid >> 1;
    const int co = (tid & 1) * 8;
    float mem[8], s[8];
#pragma unroll
    for (int j = 0; j < 8; j++) { mem[j] = 0.f; s[j] = 0.f; }
#pragma unroll
    for (int t = 0; t < NT; t++) {
        size_t xb = ((((size_t)t * NB + b) * NC1 + c0) * HH + y) * WW;
#pragma unroll
        for (int j = 0; j < 8; j++) {
            int idx = j * 256 + tid;
            int cl = idx >> 7, w = idx & 127;
            float xv = x[xb + (size_t)cl * HW + w];
            mem[j] = (mem[j] - 0.5f * s[j]) * 0.25f + xv;
            s[j] = rintf(fminf(fmaxf(mem[j], 0.f), 1.f));
            sbuf[w][cl] = __float2bfloat16(s[j]);
        }
        __syncthreads();
        uint4 v = *(const uint4*)&sbuf[wo][co];
        size_t ob = (((size_t)(t * NB + b) * HH + y) * WW + wo) * NC1 + c0 + co;
        *(uint4*)(&g_spikes[ob]) = v;
        __syncthreads();
    }
}

// ---------------- K0: split weights into bf16 hi/lo, [kk][o][c] ----------------
__global__ void wprep_kernel(const float* __restrict__ w) {
    int i = blockIdx.x * 256 + threadIdx.x;
    if (i < NW) {
        int kx = i % 3, ky = (i / 3) % 3, c = (i / 9) % NC1, o = i / (NC1 * 9);
        float v = w[i];
        __nv_bfloat16 hi = __float2bfloat16(v);
        __nv_bfloat16 lo = __float2bfloat16(v - __bfloat162float(hi));
        int dst = ((ky * 3 + kx) * NC2 + o) * NC1 + c;
        g_whi[dst] = hi;
        g_wlo[dst] = lo;
    }
}

// ---------------- K2: implicit-GEMM conv via mma.sync (base sm_103 ISA) ----
// grid (64 tiles, 32 images), 512 threads = 16 warps (4 px-groups x 4 oc-groups).
// CTA: 256 px (16y x 16x) x 128 oc, K = 9 taps x 64 ch, split-bf16 weights.
__global__ void __launch_bounds__(512, 1) conv_kernel() {
    extern __shared__ unsigned char smem[];
    const uint32_t sb = smem_u32(smem);
    const int tid = threadIdx.x;
    const int l = tid & 31, wid = tid >> 5;
    const int n = blockIdx.y;
    const int y0 = (blockIdx.x >> 3) * 16, x0 = (blockIdx.x & 7) * 16;

    // loader mapping: A (256 px x 8 chunks of 16B), B (2 halves x 128 oc x 8 chunks)
    const int apx = tid >> 1, ac0 = (tid & 1) * 4;
    const int ay = apx >> 4, ax = apx & 15;
    const int tl = tid & 255;
    const int boc = tl >> 1, bc0 = (tl & 1) * 4;
    const int half = tid >> 8;
    const __nv_bfloat16* wbase = half ? g_wlo : g_whi;

    auto issue = [&](int kk, int q) {
        const int dy = kk / 3 - 1, dx = kk % 3 - 1;
        int y = y0 + ay + dy, x = x0 + ax + dx;
        const bool ok = ((unsigned)y < HH) && ((unsigned)x < WW);
        if (!ok) { y = 0; x = 0; }
        const int sz = ok ? 16 : 0;
        unsigned long long ga = (unsigned long long)__cvta_generic_to_global(
            (void*)(g_spikes + (((size_t)n * HH + y) * WW + x) * NC1 + ac0 * 8));
        uint32_t sa = sb + q * STAGE + apx * 128;
#pragma unroll
        for (int j = 0; j < 4; j++) {
            uint32_t d = sa + (((ac0 + j) ^ (apx & 7)) << 4);
            asm volatile("cp.async.cg.shared.global [%0], [%1], 16, %2;"
                         :: "r"(d), "l"(ga + (unsigned long long)j * 16), "r"(sz)
                         : "memory");
        }
        unsigned long long gb = (unsigned long long)__cvta_generic_to_global(
            (void*)(wbase + ((size_t)kk * NC2 + boc) * NC1 + bc0 * 8));
        uint32_t sB = sb + q * STAGE + OFF_BHI + half * 16384 + boc * 128;
#pragma unroll
        for (int j = 0; j < 4; j++) {
            uint32_t d = sB + (((bc0 + j) ^ (boc & 7)) << 4);
            asm volatile("cp.async.cg.shared.global [%0], [%1], 16, 16;"
                         :: "r"(d), "l"(gb + (unsigned long long)j * 16)
                         : "memory");
        }
        asm volatile("cp.async.commit_group;" ::: "memory");
    };

    // warp geometry
    const int wm = wid & 3, wn = wid >> 2;
    const int rA = wm * 64 + ((l >> 3) & 1) * 8 + (l & 7);  // + m*16
    const int kcA = l >> 4;
    const int rA7 = rA & 7;
    const int rBb = wn * 32 + (l & 7);                      // + nn*8
    const int kcB = (l >> 3) & 1;
    const int l7 = l & 7;

    float acc[4][4][4];
#pragma unroll
    for (int m = 0; m < 4; m++)
#pragma unroll
        for (int nn = 0; nn < 4; nn++)
#pragma unroll
            for (int e = 0; e < 4; e++) acc[m][nn][e] = 0.f;

    issue(0, 0);
    for (int kk = 0; kk < 9; kk++) {
        const int q = kk & 1;
        if (kk < 8) {
            issue(kk + 1, q ^ 1);
            asm volatile("cp.async.wait_group 1;" ::: "memory");
        } else {
            asm volatile("cp.async.wait_group 0;" ::: "memory");
        }
        __syncthreads();
        const uint32_t base = sb + q * STAGE;
#pragma unroll
        for (int ks = 0; ks < 4; ks++) {
            uint32_t bh[4][2], bl[4][2];
#pragma unroll
            for (int nn = 0; nn < 4; nn++) {
                uint32_t off = (uint32_t)(rBb + nn * 8) * 128 +
                               (((ks * 2 + kcB) ^ l7) << 4);
                asm volatile(
                    "ldmatrix.sync.aligned.m8n8.x2.shared.b16 {%0,%1}, [%2];"
                    : "=r"(bh[nn][0]), "=r"(bh[nn][1])
                    : "r"(base + OFF_BHI + off));
                asm volatile(
                    "ldmatrix.sync.aligned.m8n8.x2.shared.b16 {%0,%1}, [%2];"
                    : "=r"(bl[nn][0]), "=r"(bl[nn][1])
                    : "r"(base + OFF_BLO + off));
            }
#pragma unroll
            for (int m = 0; m < 4; m++) {
                uint32_t a[4];
                uint32_t ad = base + (uint32_t)(rA + m * 16) * 128 +
                              (((ks * 2 + kcA) ^ rA7) << 4);
                asm volatile(
                    "ldmatrix.sync.aligned.m8n8.x4.shared.b16 {%0,%1,%2,%3}, [%4];"
                    : "=r"(a[0]), "=r"(a[1]), "=r"(a[2]), "=r"(a[3])
                    : "r"(ad));
#pragma unroll
                for (int nn = 0; nn < 4; nn++) {
                    mma_bf16(acc[m][nn], a, bh[nn]);
                    mma_bf16(acc[m][nn], a, bl[nn]);
                }
            }
        }
        __syncthreads();
    }

    // epilogue: direct stores to g_y [n][o][y][x]
#pragma unroll
    for (int m = 0; m < 4; m++) {
        const int y = y0 + wm * 4 + m;       // one m-tile == one image row
        const int x = x0 + (l >> 2);
#pragma unroll
        for (int nn = 0; nn < 4; nn++) {
            const int oc = wn * 32 + nn * 8 + (l & 3) * 2;
            float* p = g_y + ((size_t)n * NC2 + oc) * HW + y * WW + x;
            p[0]      = acc[m][nn][0];
            p[HW]     = acc[m][nn][1];
            p[8]      = acc[m][nn][2];
            p[HW + 8] = acc[m][nn][3];
        }
    }
}

// ---------------- K3a: per-(channel,image) partial sums ----------------
__global__ void stats_partial() {
    const int c = blockIdx.x;
    const int n = blockIdx.y;
    const float* p = g_y + ((size_t)n * NC2 + c) * HW;
    float s = 0.f, s2 = 0.f;
    for (int i = threadIdx.x; i < HW; i += 256) {
        float val = p[i];
        s += val;
        s2 += val * val;
    }
    __shared__ float rs[256], rs2[256];
    rs[threadIdx.x] = s;
    rs2[threadIdx.x] = s2;
    __syncthreads();
    for (int st = 128; st > 0; st >>= 1) {
        if (threadIdx.x < st) {
            rs[threadIdx.x] += rs[threadIdx.x + st];
            rs2[threadIdx.x] += rs2[threadIdx.x + st];
        }
        __syncthreads();
    }
    if (threadIdx.x == 0) {
        g_psum[c * NIMG + n] = rs[0];
        g_psumsq[c * NIMG + n] = rs2[0];
    }
}

// ---------------- K3b: finalize BN scale/shift ----------------
__global__ void stats_final(const float* __restrict__ gamma,
                            const float* __restrict__ beta) {
    int c = threadIdx.x;
    float s = 0.f, s2 = 0.f;
    for (int n = 0; n < NIMG; n++) {
        s += g_psum[c * NIMG + n];
        s2 += g_psumsq[c * NIMG + n];
    }
    const float inv = 1.f / (float)NELEM_PER_CH;
    float mean = s * inv;
    float var = fmaxf(s2 * inv - mean * mean, 0.f);
    float r = rsqrtf(var + 1e-5f);
    float sc = gamma[c] * r;
    g_scale[c] = sc;
    g_shift[c] = beta[c] - mean * sc;
}

// ---------------- K4: apply BN ----------------
__global__ void bn_apply(float* __restrict__ out) {
    size_t i = (size_t)blockIdx.x * 256 + threadIdx.x;   // float4 index
    const float4 vy = ((const float4*)g_y)[i];
    int c = (int)((i >> 12) & 127);
    float sc = g_scale[c], sh = g_shift[c];
    float4 o;
    o.x = fmaf(vy.x, sc, sh);
    o.y = fmaf(vy.y, sc, sh);
    o.z = fmaf(vy.z, sc, sh);
    o.w = fmaf(vy.w, sc, sh);
    ((float4*)out)[i] = o;
}

extern "C" void kernel_launch(void* const* d_in, const int* in_sizes, int n_in,
                              void* d_out, int out_size) {
    const float* x     = (const float*)d_in[0];
    const float* w     = (const float*)d_in[1];
    const float* gamma = (const float*)d_in[2];
    const float* beta  = (const float*)d_in[3];
    float* out = (float*)d_out;

    cudaFuncSetAttribute(conv_kernel, cudaFuncAttributeMaxDynamicSharedMemorySize,
                         SMEM_TOTAL);

    lif_kernel<<<dim3(NB, HH, 4), 256>>>(x);
    wprep_kernel<<<(NW + 255) / 256, 256>>>(w);
    conv_kernel<<<dim3(64, NIMG), 512, SMEM_TOTAL>>>();
    stats_partial<<<dim3(NC2, NIMG), 256>>>();
    stats_final<<<1, NC2>>>(gamma, beta);
    bn_apply<<<NY / 4 / 256, 256>>>(out);
}

// round 11
// speedup vs baseline: 3.7744x; 1.5238x over previous
#include <cuda_runtime.h>
#include <cuda_fp16.h>
#include <cstdint>

// ---------------- problem dims ----------------
#define NT 4
#define NB 8
#define NC1 64
#define NC2 128
#define HH 128
#define WW 128
#define HW 16384
#define NIMG 32
#define NSPIKES 33554432       // NIMG*NC1*HW
#define NY 67108864            // NIMG*NC2*HW
#define NELEM_PER_CH 524288
#define NW 73728
#define NCTA 2048              // conv grid size

// ---------------- conv (mma.sync) config ----------------
#define STAGE 49152            // A(32K) + B(16K)
#define OFF_B 32768
#define SMEM_TOTAL (2*STAGE)   // 98304

// ---------------- device scratch ----------------
__device__ __half g_spikes[NSPIKES];          // [n][y][x][c]  channel-last
__device__ float g_y[NY];                     // [n][o][y][x]
__device__ __half g_w[9*NC2*NC1];             // [kk][o][c] fp16 weights
__device__ float g_ps[NC2*NCTA];              // per-(ch,cta) sum
__device__ float g_pq[NC2*NCTA];              // per-(ch,cta) sumsq
__device__ float g_scale[NC2];
__device__ float g_shift[NC2];

// ---------------- helpers ----------------
__device__ __forceinline__ uint32_t smem_u32(const void* p) {
    uint32_t a;
    asm("{ .reg .u64 t; cvta.to.shared.u64 t, %1; cvt.u32.u64 %0, t; }"
        : "=r"(a) : "l"(p));
    return a;
}

__device__ __forceinline__ void mma_f16(float* d, const uint32_t* a,
                                        const uint32_t* b) {
    asm volatile(
        "mma.sync.aligned.m16n8k16.row.col.f32.f16.f16.f32 "
        "{%0,%1,%2,%3}, {%4,%5,%6,%7}, {%8,%9}, {%0,%1,%2,%3};"
        : "+f"(d[0]), "+f"(d[1]), "+f"(d[2]), "+f"(d[3])
        : "r"(a[0]), "r"(a[1]), "r"(a[2]), "r"(a[3]), "r"(b[0]), "r"(b[1]));
}

// ---------------- K1: LIF -> fp16 spikes, channel-last ----------------
// grid (8 b, 128 y, 4 cgroups), 256 threads.
__global__ void lif_kernel(const float* __restrict__ x) {
    __shared__ __half sbuf[128][24];   // 48B rows -> 16B-aligned uint4 reads
    const int b = blockIdx.x, y = blockIdx.y, cg = blockIdx.z;
    const int tid = threadIdx.x;
    const int c0 = cg * 16;
    const int wo = tid >> 1;
    const int co = (tid & 1) * 8;
    float mem[8], s[8];
#pragma unroll
    for (int j = 0; j < 8; j++) { mem[j] = 0.f; s[j] = 0.f; }
#pragma unroll
    for (int t = 0; t < NT; t++) {
        size_t xb = ((((size_t)t * NB + b) * NC1 + c0) * HH + y) * WW;
#pragma unroll
        for (int j = 0; j < 8; j++) {
            int idx = j * 256 + tid;
            int cl = idx >> 7, w = idx & 127;
            float xv = x[xb + (size_t)cl * HW + w];
            mem[j] = (mem[j] - 0.5f * s[j]) * 0.25f + xv;
            s[j] = rintf(fminf(fmaxf(mem[j], 0.f), 1.f));
            sbuf[w][cl] = __float2half_rn(s[j]);   // {0,1} exact
        }
        __syncthreads();
        uint4 v = *(const uint4*)&sbuf[wo][co];
        size_t ob = (((size_t)(t * NB + b) * HH + y) * WW + wo) * NC1 + c0 + co;
        *(uint4*)(&g_spikes[ob]) = v;
        __syncthreads();
    }
}

// ---------------- K0: weights -> fp16, [kk][o][c] ----------------
__global__ void wprep_kernel(const float* __restrict__ w) {
    int i = blockIdx.x * 256 + threadIdx.x;
    if (i < NW) {
        int kx = i % 3, ky = (i / 3) % 3, c = (i / 9) % NC1, o = i / (NC1 * 9);
        g_w[((ky * 3 + kx) * NC2 + o) * NC1 + c] = __float2half_rn(w[i]);
    }
}

// ---------------- K2: implicit-GEMM conv via mma.sync + fused BN stats ----
// grid (64 tiles, 32 images), 512 threads = 16 warps (4 px-groups x 4 oc-groups).
// CTA: 256 px (16y x 16x) x 128 oc, K = 9 taps x 64 ch, fp16 weights.
__global__ void __launch_bounds__(512, 1) conv_kernel() {
    extern __shared__ unsigned char smem[];
    const uint32_t sb = smem_u32(smem);
    const int tid = threadIdx.x;
    const int l = tid & 31, wid = tid >> 5;
    const int n = blockIdx.y;
    const int y0 = (blockIdx.x >> 3) * 16, x0 = (blockIdx.x & 7) * 16;

    // loader mapping: A (256 px x 8 chunks of 16B) by all 512 thr (4 each),
    // B (128 oc x 8 chunks) by all 512 thr (2 each)
    const int apx = tid >> 1, ac0 = (tid & 1) * 4;
    const int ay = apx >> 4, ax = apx & 15;
    const int boc = tid >> 2, bj0 = tid & 3;

    auto issue = [&](int kk, int q) {
        const int dy = kk / 3 - 1, dx = kk % 3 - 1;
        int y = y0 + ay + dy, x = x0 + ax + dx;
        const bool ok = ((unsigned)y < HH) && ((unsigned)x < WW);
        if (!ok) { y = 0; x = 0; }
        const int sz = ok ? 16 : 0;
        unsigned long long ga = (unsigned long long)__cvta_generic_to_global(
            (void*)(g_spikes + (((size_t)n * HH + y) * WW + x) * NC1 + ac0 * 8));
        uint32_t sa = sb + q * STAGE + apx * 128;
#pragma unroll
        for (int j = 0; j < 4; j++) {
            uint32_t d = sa + (((ac0 + j) ^ (apx & 7)) << 4);
            asm volatile("cp.async.cg.shared.global [%0], [%1], 16, %2;"
                         :: "r"(d), "l"(ga + (unsigned long long)j * 16), "r"(sz)
                         : "memory");
        }
        unsigned long long gb = (unsigned long long)__cvta_generic_to_global(
            (void*)(g_w + ((size_t)kk * NC2 + boc) * NC1 + bj0 * 8));
        uint32_t sB = sb + q * STAGE + OFF_B + boc * 128;
#pragma unroll
        for (int j = 0; j < 2; j++) {
            int bj = bj0 + j * 4;
            uint32_t d = sB + ((bj ^ (boc & 7)) << 4);
            asm volatile("cp.async.cg.shared.global [%0], [%1], 16, 16;"
                         :: "r"(d), "l"(gb + (unsigned long long)j * 64)
                         : "memory");
        }
        asm volatile("cp.async.commit_group;" ::: "memory");
    };

    // warp geometry
    const int wm = wid & 3, wn = wid >> 2;
    const int rA = wm * 64 + ((l >> 3) & 1) * 8 + (l & 7);  // + m*16
    const int kcA = l >> 4;
    const int rA7 = rA & 7;
    const int rBb = wn * 32 + (l & 7);                      // + nn*8
    const int kcB = (l >> 3) & 1;
    const int l7 = l & 7;

    float acc[4][4][4];
#pragma unroll
    for (int m = 0; m < 4; m++)
#pragma unroll
        for (int nn = 0; nn < 4; nn++)
#pragma unroll
            for (int e = 0; e < 4; e++) acc[m][nn][e] = 0.f;

    issue(0, 0);
    for (int kk = 0; kk < 9; kk++) {
        const int q = kk & 1;
        if (kk < 8) {
            issue(kk + 1, q ^ 1);
            asm volatile("cp.async.wait_group 1;" ::: "memory");
        } else {
            asm volatile("cp.async.wait_group 0;" ::: "memory");
        }
        __syncthreads();
        const uint32_t base = sb + q * STAGE;
#pragma unroll
        for (int ks = 0; ks < 4; ks++) {
            uint32_t bf[4][2];
#pragma unroll
            for (int nn = 0; nn < 4; nn++) {
                uint32_t off = (uint32_t)(rBb + nn * 8) * 128 +
                               (((ks * 2 + kcB) ^ l7) << 4);
                asm volatile(
                    "ldmatrix.sync.aligned.m8n8.x2.shared.b16 {%0,%1}, [%2];"
                    : "=r"(bf[nn][0]), "=r"(bf[nn][1])
                    : "r"(base + OFF_B + off));
            }
#pragma unroll
            for (int m = 0; m < 4; m++) {
                uint32_t a[4];
                uint32_t ad = base + (uint32_t)(rA + m * 16) * 128 +
                              (((ks * 2 + kcA) ^ rA7) << 4);
                asm volatile(
                    "ldmatrix.sync.aligned.m8n8.x4.shared.b16 {%0,%1,%2,%3}, [%4];"
                    : "=r"(a[0]), "=r"(a[1]), "=r"(a[2]), "=r"(a[3])
                    : "r"(ad));
#pragma unroll
                for (int nn = 0; nn < 4; nn++)
                    mma_f16(acc[m][nn], a, bf[nn]);
            }
        }
        __syncthreads();
    }

    // ---- epilogue 1: direct stores to g_y [n][o][y][x] ----
#pragma unroll
    for (int m = 0; m < 4; m++) {
        const int y = y0 + wm * 4 + m;       // one m-tile == one image row
        const int x = x0 + (l >> 2);
#pragma unroll
        for (int nn = 0; nn < 4; nn++) {
            const int oc = wn * 32 + nn * 8 + (l & 3) * 2;
            float* p = g_y + ((size_t)n * NC2 + oc) * HW + y * WW + x;
            p[0]      = acc[m][nn][0];
            p[HW]     = acc[m][nn][1];
            p[8]      = acc[m][nn][2];
            p[HW + 8] = acc[m][nn][3];
        }
    }

    // ---- epilogue 2: fused deterministic BN partial stats ----
    // per-lane: sum/sumsq over the 8 pixels this lane holds, per (nn, col)
    float* sred = (float*)smem;  // [16 wid][4 nn][4 sel][4: s0,s1,q0,q1] = 4KB
#pragma unroll
    for (int nn = 0; nn < 4; nn++) {
        float s0 = 0.f, s1 = 0.f, q0 = 0.f, q1 = 0.f;
#pragma unroll
        for (int m = 0; m < 4; m++) {
            float v0 = acc[m][nn][0], v1 = acc[m][nn][1];
            float v2 = acc[m][nn][2], v3 = acc[m][nn][3];
            s0 += v0 + v2; q0 += v0 * v0 + v2 * v2;
            s1 += v1 + v3; q1 += v1 * v1 + v3 * v3;
        }
#pragma unroll
        for (int o = 4; o <= 16; o <<= 1) {   // reduce over x-lanes (bits 2..4)
            s0 += __shfl_xor_sync(0xffffffffu, s0, o);
            s1 += __shfl_xor_sync(0xffffffffu, s1, o);
            q0 += __shfl_xor_sync(0xffffffffu, q0, o);
            q1 += __shfl_xor_sync(0xffffffffu, q1, o);
        }
        if (l < 4) {
            float* p = sred + ((wid * 4 + nn) * 4 + l) * 4;
            p[0] = s0; p[1] = s1; p[2] = q0; p[3] = q1;
        }
    }
    __syncthreads();
    if (tid < NC2) {
        const int c = tid;
        const int cwn = c >> 5, cnn = (c >> 3) & 3, csel = (c >> 1) & 3, ccol = c & 1;
        float S = 0.f, Q = 0.f;
#pragma unroll
        for (int wm2 = 0; wm2 < 4; wm2++) {
            const float* p = sred + (((cwn * 4 + wm2) * 4 + cnn) * 4 + csel) * 4;
            S += p[ccol];
            Q += p[2 + ccol];
        }
        const int cta = blockIdx.y * 64 + blockIdx.x;
        g_ps[c * NCTA + cta] = S;
        g_pq[c * NCTA + cta] = Q;
    }
}

// ---------------- K3: finalize BN scale/shift (128 blocks) ----------------
__global__ void stats_final(const float* __restrict__ gamma,
                            const float* __restrict__ beta) {
    const int c = blockIdx.x;
    const int tid = threadIdx.x;
    float s = 0.f, q = 0.f;
    for (int i = tid; i < NCTA; i += 256) {
        s += g_ps[c * NCTA + i];
        q += g_pq[c * NCTA + i];
    }
    __shared__ float rs[256], rq[256];
    rs[tid] = s; rq[tid] = q;
    __syncthreads();
    for (int st = 128; st > 0; st >>= 1) {
        if (tid < st) { rs[tid] += rs[tid + st]; rq[tid] += rq[tid + st]; }
        __syncthreads();
    }
    if (tid == 0) {
        const float inv = 1.f / (float)NELEM_PER_CH;
        float mean = rs[0] * inv;
        float var = fmaxf(rq[0] * inv - mean * mean, 0.f);
        float r = rsqrtf(var + 1e-5f);
        float sc = gamma[c] * r;
        g_scale[c] = sc;
        g_shift[c] = beta[c] - mean * sc;
    }
}

// ---------------- K4: apply BN ----------------
__global__ void bn_apply(float* __restrict__ out) {
    size_t i = (size_t)blockIdx.x * 256 + threadIdx.x;   // float4 index
    const float4 vy = ((const float4*)g_y)[i];
    int c = (int)((i >> 12) & 127);
    float sc = g_scale[c], sh = g_shift[c];
    float4 o;
    o.x = fmaf(vy.x, sc, sh);
    o.y = fmaf(vy.y, sc, sh);
    o.z = fmaf(vy.z, sc, sh);
    o.w = fmaf(vy.w, sc, sh);
    ((float4*)out)[i] = o;
}

extern "C" void kernel_launch(void* const* d_in, const int* in_sizes, int n_in,
                              void* d_out, int out_size) {
    const float* x     = (const float*)d_in[0];
    const float* w     = (const float*)d_in[1];
    const float* gamma = (const float*)d_in[2];
    const float* beta  = (const float*)d_in[3];
    float* out = (float*)d_out;

    cudaFuncSetAttribute(conv_kernel, cudaFuncAttributeMaxDynamicSharedMemorySize,
                         SMEM_TOTAL);

    lif_kernel<<<dim3(NB, HH, 4), 256>>>(x);
    wprep_kernel<<<(NW + 255) / 256, 256>>>(w);
    conv_kernel<<<dim3(64, NIMG), 512, SMEM_TOTAL>>>();
    stats_final<<<NC2, 256>>>(gamma, beta);
    bn_apply<<<NY / 4 / 256, 256>>>(out);
}

// round 13
// speedup vs baseline: 4.6164x; 1.2231x over previous
#include <cuda_runtime.h>
#include <cuda_fp16.h>
#include <cstdint>

// ---------------- problem dims ----------------
#define NT 4
#define NB 8
#define NC1 64
#define NC2 128
#define HH 128
#define WW 128
#define HW 16384
#define NIMG 32
#define NSPIKES 33554432       // NIMG*NC1*HW
#define NY 67108864            // NIMG*NC2*HW
#define NELEM_PER_CH 524288
#define NW 73728
#define NCTA 2048              // conv grid size

// ---------------- conv (mma.sync) config ----------------
#define STAGE 49152            // A(32K) + B(16K)
#define OFF_B 32768
#define SMEM_TOTAL (3*STAGE)   // 147456 (3-stage ring)

// ---------------- device scratch ----------------
__device__ __half g_spikes[NSPIKES];          // [n][y][x][c]  channel-last
__device__ __half g_y[NY];                    // [n][o][y][x]  fp16 intermediate
__device__ __half g_w[9*NC2*NC1];             // [kk][o][c] fp16 weights
__device__ float g_ps[NC2*NCTA];              // per-(ch,cta) sum
__device__ float g_pq[NC2*NCTA];              // per-(ch,cta) sumsq
__device__ float g_scale[NC2];
__device__ float g_shift[NC2];

// ---------------- helpers ----------------
__device__ __forceinline__ uint32_t smem_u32(const void* p) {
    uint32_t a;
    asm("{ .reg .u64 t; cvta.to.shared.u64 t, %1; cvt.u32.u64 %0, t; }"
        : "=r"(a) : "l"(p));
    return a;
}

__device__ __forceinline__ void mma_f16(float* d, const uint32_t* a,
                                        const uint32_t* b) {
    asm volatile(
        "mma.sync.aligned.m16n8k16.row.col.f32.f16.f16.f32 "
        "{%0,%1,%2,%3}, {%4,%5,%6,%7}, {%8,%9}, {%0,%1,%2,%3};"
        : "+f"(d[0]), "+f"(d[1]), "+f"(d[2]), "+f"(d[3])
        : "r"(a[0]), "r"(a[1]), "r"(a[2]), "r"(a[3]), "r"(b[0]), "r"(b[1]));
}

// ---------------- K1: LIF -> fp16 spikes, channel-last ----------------
// grid (8 b, 128 y, 4 cgroups), 256 threads.
__global__ void lif_kernel(const float* __restrict__ x) {
    __shared__ __half sbuf[128][24];   // 48B rows -> 16B-aligned uint4 reads
    const int b = blockIdx.x, y = blockIdx.y, cg = blockIdx.z;
    const int tid = threadIdx.x;
    const int c0 = cg * 16;
    const int wo = tid >> 1;
    const int co = (tid & 1) * 8;
    float mem[8], s[8];
#pragma unroll
    for (int j = 0; j < 8; j++) { mem[j] = 0.f; s[j] = 0.f; }
#pragma unroll
    for (int t = 0; t < NT; t++) {
        size_t xb = ((((size_t)t * NB + b) * NC1 + c0) * HH + y) * WW;
#pragma unroll
        for (int j = 0; j < 8; j++) {
            int idx = j * 256 + tid;
            int cl = idx >> 7, w = idx & 127;
            float xv = x[xb + (size_t)cl * HW + w];
            mem[j] = (mem[j] - 0.5f * s[j]) * 0.25f + xv;
            s[j] = rintf(fminf(fmaxf(mem[j], 0.f), 1.f));
            sbuf[w][cl] = __float2half_rn(s[j]);   // {0,1} exact
        }
        __syncthreads();
        uint4 v = *(const uint4*)&sbuf[wo][co];
        size_t ob = (((size_t)(t * NB + b) * HH + y) * WW + wo) * NC1 + c0 + co;
        *(uint4*)(&g_spikes[ob]) = v;
        __syncthreads();
    }
}

// ---------------- K0: weights -> fp16, [kk][o][c] ----------------
__global__ void wprep_kernel(const float* __restrict__ w) {
    int i = blockIdx.x * 256 + threadIdx.x;
    if (i < NW) {
        int kx = i % 3, ky = (i / 3) % 3, c = (i / 9) % NC1, o = i / (NC1 * 9);
        g_w[((ky * 3 + kx) * NC2 + o) * NC1 + c] = __float2half_rn(w[i]);
    }
}

// ---------------- K2: implicit-GEMM conv via mma.sync + fused BN stats ----
// grid (64 tiles, 32 images), 512 threads = 16 warps (4 px-groups x 4 oc-groups).
// CTA: 256 px (16y x 16x) x 128 oc, K = 9 taps x 64 ch, fp16 weights.
// Pixel p -> (y = p>>4, x = ((p&7)<<1)|((p>>3)&1)) so fragment rows p, p+8
// are adjacent x -> packed __half2 full-sector stores.
__global__ void __launch_bounds__(512, 1) conv_kernel() {
    extern __shared__ unsigned char smem[];
    const uint32_t sb = smem_u32(smem);
    const int tid = threadIdx.x;
    const int l = tid & 31, wid = tid >> 5;
    const int n = blockIdx.y;
    const int y0 = (blockIdx.x >> 3) * 16, x0 = (blockIdx.x & 7) * 16;

    // loader mapping: A (256 px x 8 chunks of 16B) by all 512 thr (4 each),
    // B (128 oc x 8 chunks) by all 512 thr (2 each)
    const int apx = tid >> 1, ac0 = (tid & 1) * 4;
    const int ay = apx >> 4;
    const int ax = ((apx & 7) << 1) | ((apx >> 3) & 1);   // permuted x
    const int boc = tid >> 2, bj0 = tid & 3;

    auto issue = [&](int kk, int q) {
        const int dy = kk / 3 - 1, dx = kk % 3 - 1;
        int y = y0 + ay + dy, x = x0 + ax + dx;
        const bool ok = ((unsigned)y < HH) && ((unsigned)x < WW);
        if (!ok) { y = 0; x = 0; }
        const int sz = ok ? 16 : 0;
        unsigned long long ga = (unsigned long long)__cvta_generic_to_global(
            (void*)(g_spikes + (((size_t)n * HH + y) * WW + x) * NC1 + ac0 * 8));
        uint32_t sa = sb + q * STAGE + apx * 128;
#pragma unroll
        for (int j = 0; j < 4; j++) {
            uint32_t d = sa + (((ac0 + j) ^ (apx & 7)) << 4);
            asm volatile("cp.async.cg.shared.global [%0], [%1], 16, %2;"
                         :: "r"(d), "l"(ga + (unsigned long long)j * 16), "r"(sz)
                         : "memory");
        }
        unsigned long long gb = (unsigned long long)__cvta_generic_to_global(
            (void*)(g_w + ((size_t)kk * NC2 + boc) * NC1 + bj0 * 8));
        uint32_t sB = sb + q * STAGE + OFF_B + boc * 128;
#pragma unroll
        for (int j = 0; j < 2; j++) {
            int bj = bj0 + j * 4;
            uint32_t d = sB + ((bj ^ (boc & 7)) << 4);
            asm volatile("cp.async.cg.shared.global [%0], [%1], 16, 16;"
                         :: "r"(d), "l"(gb + (unsigned long long)j * 64)
                         : "memory");
        }
        asm volatile("cp.async.commit_group;" ::: "memory");
    };

    // warp geometry
    const int wm = wid & 3, wn = wid >> 2;
    const int rA = wm * 64 + ((l >> 3) & 1) * 8 + (l & 7);  // + m*16
    const int kcA = l >> 4;
    const int rA7 = rA & 7;
    const int rBb = wn * 32 + (l & 7);                      // + nn*8
    const int kcB = (l >> 3) & 1;
    const int l7 = l & 7;

    float acc[4][4][4];
#pragma unroll
    for (int m = 0; m < 4; m++)
#pragma unroll
        for (int nn = 0; nn < 4; nn++)
#pragma unroll
            for (int e = 0; e < 4; e++) acc[m][nn][e] = 0.f;

    issue(0, 0);
    int stage_of[16];  // kk -> stage
#pragma unroll
    for (int kk = 0; kk < 10; kk++) stage_of[kk] = kk % 3;

    for (int kk = 0; kk < 9; kk++) {
        const int q = stage_of[kk];
        if (kk < 8) {
            issue(kk + 1, stage_of[kk + 1]);
            asm volatile("cp.async.wait_group 1;" ::: "memory");
        } else {
            asm volatile("cp.async.wait_group 0;" ::: "memory");
        }
        __syncthreads();
        const uint32_t base = sb + q * STAGE;
#pragma unroll
        for (int ks = 0; ks < 4; ks++) {
            uint32_t bf[4][2];
#pragma unroll
            for (int nn = 0; nn < 4; nn++) {
                uint32_t off = (uint32_t)(rBb + nn * 8) * 128 +
                               (((ks * 2 + kcB) ^ l7) << 4);
                asm volatile(
                    "ldmatrix.sync.aligned.m8n8.x2.shared.b16 {%0,%1}, [%2];"
                    : "=r"(bf[nn][0]), "=r"(bf[nn][1])
                    : "r"(base + OFF_B + off));
            }
#pragma unroll
            for (int m = 0; m < 4; m++) {
                uint32_t a[4];
                uint32_t ad = base + (uint32_t)(rA + m * 16) * 128 +
                              (((ks * 2 + kcA) ^ rA7) << 4);
                asm volatile(
                    "ldmatrix.sync.aligned.m8n8.x4.shared.b16 {%0,%1,%2,%3}, [%4];"
                    : "=r"(a[0]), "=r"(a[1]), "=r"(a[2]), "=r"(a[3])
                    : "r"(ad));
#pragma unroll
                for (int nn = 0; nn < 4; nn++)
                    mma_f16(acc[m][nn], a, bf[nn]);
            }
        }
    }

    // ---- epilogue 1: packed fp16 stores to g_y [n][o][y][x] ----
    // fragment rows (l>>2) and (l>>2)+8 are x and x+1 under the permutation
#pragma unroll
    for (int m = 0; m < 4; m++) {
        const int y = y0 + wm * 4 + m;
        const int x = x0 + ((l >> 2) << 1);
#pragma unroll
        for (int nn = 0; nn < 4; nn++) {
            const int oc = wn * 32 + nn * 8 + (l & 3) * 2;
            __half* p = g_y + ((size_t)n * NC2 + oc) * HW + y * WW + x;
            *(__half2*)p = __floats2half2_rn(acc[m][nn][0], acc[m][nn][2]);
            *(__half2*)(p + HW) = __floats2half2_rn(acc[m][nn][1], acc[m][nn][3]);
        }
    }

    // ---- epilogue 2: fused deterministic BN partial stats (fp32 accs) ----
    float* sred = (float*)smem;  // [16 wid][4 nn][4 sel][4: s0,s1,q0,q1] = 4KB
#pragma unroll
    for (int nn = 0; nn < 4; nn++) {
        float s0 = 0.f, s1 = 0.f, q0 = 0.f, q1 = 0.f;
#pragma unroll
        for (int m = 0; m < 4; m++) {
            float v0 = acc[m][nn][0], v1 = acc[m][nn][1];
            float v2 = acc[m][nn][2], v3 = acc[m][nn][3];
            s0 += v0 + v2; q0 += v0 * v0 + v2 * v2;
            s1 += v1 + v3; q1 += v1 * v1 + v3 * v3;
        }
#pragma unroll
        for (int o = 4; o <= 16; o <<= 1) {   // reduce over x-lanes (bits 2..4)
            s0 += __shfl_xor_sync(0xffffffffu, s0, o);
            s1 += __shfl_xor_sync(0xffffffffu, s1, o);
            q0 += __shfl_xor_sync(0xffffffffu, q0, o);
            q1 += __shfl_xor_sync(0xffffffffu, q1, o);
        }
        if (l < 4) {
            float* p = sred + ((wid * 4 + nn) * 4 + l) * 4;
            p[0] = s0; p[1] = s1; p[2] = q0; p[3] = q1;
        }
    }
    __syncthreads();
    if (tid < NC2) {
        const int c = tid;
        const int cwn = c >> 5, cnn = (c >> 3) & 3, csel = (c >> 1) & 3, ccol = c & 1;
        float S = 0.f, Q = 0.f;
#pragma unroll
        for (int wm2 = 0; wm2 < 4; wm2++) {
            const float* p = sred + (((cwn * 4 + wm2) * 4 + cnn) * 4 + csel) * 4;
            S += p[ccol];
            Q += p[2 + ccol];
        }
        const int cta = blockIdx.y * 64 + blockIdx.x;
        g_ps[c * NCTA + cta] = S;
        g_pq[c * NCTA + cta] = Q;
    }
}

// ---------------- K3: finalize BN scale/shift (128 blocks) ----------------
__global__ void stats_final(const float* __restrict__ gamma,
                            const float* __restrict__ beta) {
    const int c = blockIdx.x;
    const int tid = threadIdx.x;
    float s = 0.f, q = 0.f;
    for (int i = tid; i < NCTA; i += 256) {
        s += g_ps[c * NCTA + i];
        q += g_pq[c * NCTA + i];
    }
    __shared__ float rs[256], rq[256];
    rs[tid] = s; rq[tid] = q;
    __syncthreads();
    for (int st = 128; st > 0; st >>= 1) {
        if (tid < st) { rs[tid] += rs[tid + st]; rq[tid] += rq[tid + st]; }
        __syncthreads();
    }
    if (tid == 0) {
        const float inv = 1.f / (float)NELEM_PER_CH;
        float mean = rs[0] * inv;
        float var = fmaxf(rq[0] * inv - mean * mean, 0.f);
        float r = rsqrtf(var + 1e-5f);
        float sc = gamma[c] * r;
        g_scale[c] = sc;
        g_shift[c] = beta[c] - mean * sc;
    }
}

// ---------------- K4: apply BN (fp16 in, fp32 out) ----------------
__global__ void bn_apply(float* __restrict__ out) {
    size_t i = (size_t)blockIdx.x * 256 + threadIdx.x;   // uint4 index (8 halves)
    const uint4 v = ((const uint4*)g_y)[i];
    int c = (int)((i >> 11) & 127);   // elem base = i*8; channel = base>>14 & 127
    float sc = g_scale[c], sh = g_shift[c];
    float2 f0 = __half22float2(*(const __half2*)&v.x);
    float2 f1 = __half22float2(*(const __half2*)&v.y);
    float2 f2 = __half22float2(*(const __half2*)&v.z);
    float2 f3 = __half22float2(*(const __half2*)&v.w);
    float4 o0, o1;
    o0.x = fmaf(f0.x, sc, sh); o0.y = fmaf(f0.y, sc, sh);
    o0.z = fmaf(f1.x, sc, sh); o0.w = fmaf(f1.y, sc, sh);
    o1.x = fmaf(f2.x, sc, sh); o1.y = fmaf(f2.y, sc, sh);
    o1.z = fmaf(f3.x, sc, sh); o1.w = fmaf(f3.y, sc, sh);
    ((float4*)out)[i * 2]     = o0;
    ((float4*)out)[i * 2 + 1] = o1;
}

extern "C" void kernel_launch(void* const* d_in, const int* in_sizes, int n_in,
                              void* d_out, int out_size) {
    const float* x     = (const float*)d_in[0];
    const float* w     = (const float*)d_in[1];
    const float* gamma = (const float*)d_in[2];
    const float* beta  = (const float*)d_in[3];
    float* out = (float*)d_out;

    cudaFuncSetAttribute(conv_kernel, cudaFuncAttributeMaxDynamicSharedMemorySize,
                         SMEM_TOTAL);

    lif_kernel<<<dim3(NB, HH, 4), 256>>>(x);
    wprep_kernel<<<(NW + 255) / 256, 256>>>(w);
    conv_kernel<<<dim3(64, NIMG), 512, SMEM_TOTAL>>>();
    stats_final<<<NC2, 256>>>(gamma, beta);
    bn_apply<<<NY / 8 / 256, 256>>>(out);
}

// round 14
// speedup vs baseline: 5.3693x; 1.1631x over previous
#include <cuda_runtime.h>
#include <cuda_fp16.h>
#include <cstdint>

// ---------------- problem dims ----------------
#define NT 4
#define NB 8
#define NC1 64
#define NC2 128
#define HH 128
#define WW 128
#define HW 16384
#define NIMG 32
#define NSPIKES 33554432       // NIMG*NC1*HW
#define NY 67108864            // NIMG*NC2*HW
#define NELEM_PER_CH 524288
#define NW 73728
#define NTILES 2048            // 32 images x 64 tiles (16x16 px)

// ---------------- conv smem layout ----------------
#define B_BYTES 147456         // 9 taps x 128 oc x 64 ch fp16, resident
#define HALO_BYTES 41472       // 324 rows (18x18) x 128 B
#define SMEM_TOTAL (B_BYTES + 2*HALO_BYTES)   // 230400

// ---------------- device scratch ----------------
__device__ __half g_spikes[NSPIKES];          // [n][y][x][c]  channel-last
__device__ __half g_y[NY];                    // [n][o][y][x]  fp16 intermediate
__device__ __half g_w[9*NC2*NC1];             // [kk][o][c] fp16 weights
__device__ float g_ps[NC2*NTILES];            // per-(ch,tile) sum
__device__ float g_pq[NC2*NTILES];            // per-(ch,tile) sumsq
__device__ float g_scale[NC2];
__device__ float g_shift[NC2];

// ---------------- helpers ----------------
__device__ __forceinline__ uint32_t smem_u32(const void* p) {
    uint32_t a;
    asm("{ .reg .u64 t; cvta.to.shared.u64 t, %1; cvt.u32.u64 %0, t; }"
        : "=r"(a) : "l"(p));
    return a;
}

__device__ __forceinline__ void mma_f16(float* d, const uint32_t* a,
                                        const uint32_t* b) {
    asm volatile(
        "mma.sync.aligned.m16n8k16.row.col.f32.f16.f16.f32 "
        "{%0,%1,%2,%3}, {%4,%5,%6,%7}, {%8,%9}, {%0,%1,%2,%3};"
        : "+f"(d[0]), "+f"(d[1]), "+f"(d[2]), "+f"(d[3])
        : "r"(a[0]), "r"(a[1]), "r"(a[2]), "r"(a[3]), "r"(b[0]), "r"(b[1]));
}

// ---------------- K1: LIF -> fp16 spikes, channel-last ----------------
__global__ void lif_kernel(const float* __restrict__ x) {
    __shared__ __half sbuf[128][24];   // 48B rows -> 16B-aligned uint4 reads
    const int b = blockIdx.x, y = blockIdx.y, cg = blockIdx.z;
    const int tid = threadIdx.x;
    const int c0 = cg * 16;
    const int wo = tid >> 1;
    const int co = (tid & 1) * 8;
    float mem[8], s[8];
#pragma unroll
    for (int j = 0; j < 8; j++) { mem[j] = 0.f; s[j] = 0.f; }
#pragma unroll
    for (int t = 0; t < NT; t++) {
        size_t xb = ((((size_t)t * NB + b) * NC1 + c0) * HH + y) * WW;
#pragma unroll
        for (int j = 0; j < 8; j++) {
            int idx = j * 256 + tid;
            int cl = idx >> 7, w = idx & 127;
            float xv = __ldcs(&x[xb + (size_t)cl * HW + w]);   // streaming
            mem[j] = (mem[j] - 0.5f * s[j]) * 0.25f + xv;
            s[j] = rintf(fminf(fmaxf(mem[j], 0.f), 1.f));
            sbuf[w][cl] = __float2half_rn(s[j]);   // {0,1} exact
        }
        __syncthreads();
        uint4 v = *(const uint4*)&sbuf[wo][co];
        size_t ob = (((size_t)(t * NB + b) * HH + y) * WW + wo) * NC1 + c0 + co;
        *(uint4*)(&g_spikes[ob]) = v;
        __syncthreads();
    }
}

// ---------------- K0: weights -> fp16, [kk][o][c] ----------------
__global__ void wprep_kernel(const float* __restrict__ w) {
    int i = blockIdx.x * 256 + threadIdx.x;
    if (i < NW) {
        int kx = i % 3, ky = (i / 3) % 3, c = (i / 9) % NC1, o = i / (NC1 * 9);
        g_w[((ky * 3 + kx) * NC2 + o) * NC1 + c] = __float2half_rn(w[i]);
    }
}

// ---------------- K2: persistent halo implicit-GEMM conv + fused stats ----
// grid = #SMs, 512 threads = 16 warps (4 px x 4 oc). Tile: 256 px x 128 oc.
// B (all 9 taps) resident in smem; per tile a single 18x18x64 halo load feeds
// all 36 MMA k-steps via per-lane-addressed ldmatrix (no per-tap barriers).
__global__ void __launch_bounds__(512, 1) conv_kernel(int nsm) {
    extern __shared__ unsigned char smem[];
    const uint32_t sb = smem_u32(smem);
    const int tid = threadIdx.x;
    const int l = tid & 31, wid = tid >> 5;
    const int wm = wid & 3, wn = wid >> 2;

    // ---- A-side per-lane constants ----
    const int kcA = l >> 4;
    const int xl = ((l & 7) << 1) | ((l >> 3) & 1);   // permuted x of this lane's rows
    const int hm0 = (wm * 4) * 18 + xl;               // + m*18 + dk -> halo row
    // ---- B-side per-lane constants ----
    const int rBb = wn * 32 + (l & 7);
    const int kcB = (l >> 3) & 1;
    const int l7 = l & 7;

    // ---- load resident B: 1152 rows x 128 B, swizzled by row&7 ----
#pragma unroll
    for (int j = 0; j < 18; j++) {
        int cid = tid + j * 512;          // 9216 chunks of 16 B
        int r = cid >> 3, cc = cid & 7;
        unsigned long long src = (unsigned long long)__cvta_generic_to_global(
            (void*)(g_w + (size_t)r * 64 + cc * 8));
        uint32_t dst = sb + (uint32_t)r * 128 + ((cc ^ (r & 7)) << 4);
        asm volatile("cp.async.cg.shared.global [%0], [%1], 16, 16;"
                     :: "r"(dst), "l"(src) : "memory");
    }

    auto issue_halo = [&](int t, int q) {
        const int n = t >> 6;
        const int gy0 = ((t >> 3) & 7) * 16 - 1;
        const int gx0 = (t & 7) * 16 - 1;
        const uint32_t hb = sb + B_BYTES + (uint32_t)q * HALO_BYTES;
#pragma unroll
        for (int j = 0; j < 6; j++) {
            int cid = tid + j * 512;      // 2592 chunks of 16 B
            if (cid < 2592) {
                int hr = cid >> 3, cc = cid & 7;
                int hy = hr / 18;
                int hx = hr - hy * 18;
                int gy = gy0 + hy, gx = gx0 + hx;
                bool ok = ((unsigned)gy < HH) && ((unsigned)gx < WW);
                int cgy = ok ? gy : 0, cgx = ok ? gx : 0;
                unsigned long long src =
                    (unsigned long long)__cvta_generic_to_global(
                        (void*)(g_spikes +
                                (((size_t)n * HH + cgy) * WW + cgx) * NC1 + cc * 8));
                uint32_t dst = hb + (uint32_t)hr * 128 +
                               ((cc ^ ((hr >> 1) & 7)) << 4);
                int sz = ok ? 16 : 0;
                asm volatile("cp.async.cg.shared.global [%0], [%1], 16, %2;"
                             :: "r"(dst), "l"(src), "r"(sz) : "memory");
            }
        }
        asm volatile("cp.async.commit_group;" ::: "memory");
    };

    int tile = blockIdx.x;
    issue_halo(tile, 0);   // commits B + halo0 as group 0
    int it = 0;
    float acc[4][4][4];

    while (tile < NTILES) {
        asm volatile("cp.async.wait_group 0;" ::: "memory");
        __syncthreads();                               // barrier 1: halo ready
        const int nxt = tile + nsm;
        if (nxt < NTILES) issue_halo(nxt, (it + 1) & 1);
        const uint32_t hs = sb + B_BYTES + (uint32_t)(it & 1) * HALO_BYTES;

#pragma unroll
        for (int m = 0; m < 4; m++)
#pragma unroll
            for (int nn = 0; nn < 4; nn++)
#pragma unroll
                for (int e = 0; e < 4; e++) acc[m][nn][e] = 0.f;

        // ---- 9 taps x 4 k-steps, no barriers, no waits ----
#pragma unroll 1
        for (int dy = 0; dy < 3; dy++) {
#pragma unroll 1
            for (int dx = 0; dx < 3; dx++) {
                const int dk = dy * 18 + dx;
                const uint32_t bB = sb + (uint32_t)(dy * 3 + dx) * 16384;
#pragma unroll
                for (int ks = 0; ks < 4; ks++) {
                    uint32_t bf[4][2];
#pragma unroll
                    for (int nn = 0; nn < 4; nn++) {
                        uint32_t off = (uint32_t)(rBb + nn * 8) * 128 +
                                       (((ks * 2 + kcB) ^ l7) << 4);
                        asm volatile(
                            "ldmatrix.sync.aligned.m8n8.x2.shared.b16 {%0,%1}, [%2];"
                            : "=r"(bf[nn][0]), "=r"(bf[nn][1])
                            : "r"(bB + off));
                    }
#pragma unroll
                    for (int m = 0; m < 4; m++) {
                        const int hr = hm0 + m * 18 + dk;
                        uint32_t ad = hs + (uint32_t)hr * 128 +
                                      (((ks * 2 + kcA) ^ ((hr >> 1) & 7)) << 4);
                        uint32_t a[4];
                        asm volatile(
                            "ldmatrix.sync.aligned.m8n8.x4.shared.b16 {%0,%1,%2,%3}, [%4];"
                            : "=r"(a[0]), "=r"(a[1]), "=r"(a[2]), "=r"(a[3])
                            : "r"(ad));
#pragma unroll
                        for (int nn = 0; nn < 4; nn++)
                            mma_f16(acc[m][nn], a, bf[nn]);
                    }
                }
            }
        }

        // ---- epilogue 1: packed fp16 y stores ----
        const int n = tile >> 6;
        const int ty0 = ((tile >> 3) & 7) * 16, tx0 = (tile & 7) * 16;
#pragma unroll
        for (int m = 0; m < 4; m++) {
            const int y = ty0 + wm * 4 + m;
            const int x = tx0 + ((l >> 2) << 1);
#pragma unroll
            for (int nn = 0; nn < 4; nn++) {
                const int oc = wn * 32 + nn * 8 + (l & 3) * 2;
                __half* p = g_y + ((size_t)n * NC2 + oc) * HW + y * WW + x;
                *(__half2*)p = __floats2half2_rn(acc[m][nn][0], acc[m][nn][2]);
                *(__half2*)(p + HW) = __floats2half2_rn(acc[m][nn][1], acc[m][nn][3]);
            }
        }

        __syncthreads();   // barrier 2: MMA reads of this halo stage done
        // ---- epilogue 2: fused BN partial stats (sred aliases dead stage) ----
        float* sred = (float*)(smem + B_BYTES + (size_t)(it & 1) * HALO_BYTES);
#pragma unroll
        for (int nn = 0; nn < 4; nn++) {
            float s0 = 0.f, s1 = 0.f, q0 = 0.f, q1 = 0.f;
#pragma unroll
            for (int m = 0; m < 4; m++) {
                float v0 = acc[m][nn][0], v1 = acc[m][nn][1];
                float v2 = acc[m][nn][2], v3 = acc[m][nn][3];
                s0 += v0 + v2; q0 += v0 * v0 + v2 * v2;
                s1 += v1 + v3; q1 += v1 * v1 + v3 * v3;
            }
#pragma unroll
            for (int o = 4; o <= 16; o <<= 1) {
                s0 += __shfl_xor_sync(0xffffffffu, s0, o);
                s1 += __shfl_xor_sync(0xffffffffu, s1, o);
                q0 += __shfl_xor_sync(0xffffffffu, q0, o);
                q1 += __shfl_xor_sync(0xffffffffu, q1, o);
            }
            if (l < 4) {
                float* p = sred + ((wid * 4 + nn) * 4 + l) * 4;
                p[0] = s0; p[1] = s1; p[2] = q0; p[3] = q1;
            }
        }
        __syncthreads();   // barrier 3
        if (tid < NC2) {
            const int c = tid;
            const int cwn = c >> 5, cnn = (c >> 3) & 3, csel = (c >> 1) & 3,
                      ccol = c & 1;
            float S = 0.f, Q = 0.f;
#pragma unroll
            for (int wm2 = 0; wm2 < 4; wm2++) {
                const float* p = sred + (((cwn * 4 + wm2) * 4 + cnn) * 4 + csel) * 4;
                S += p[ccol];
                Q += p[2 + ccol];
            }
            g_ps[c * NTILES + tile] = S;
            g_pq[c * NTILES + tile] = Q;
        }
        tile = nxt;
        it++;
    }
}

// ---------------- K3: finalize BN scale/shift ----------------
__global__ void stats_final(const float* __restrict__ gamma,
                            const float* __restrict__ beta) {
    const int c = blockIdx.x;
    const int tid = threadIdx.x;
    float s = 0.f, q = 0.f;
    for (int i = tid; i < NTILES; i += 1024) {
        s += g_ps[c * NTILES + i];
        q += g_pq[c * NTILES + i];
    }
    __shared__ float rs[1024], rq[1024];
    rs[tid] = s; rq[tid] = q;
    __syncthreads();
    for (int st = 512; st > 0; st >>= 1) {
        if (tid < st) { rs[tid] += rs[tid + st]; rq[tid] += rq[tid + st]; }
        __syncthreads();
    }
    if (tid == 0) {
        const float inv = 1.f / (float)NELEM_PER_CH;
        float mean = rs[0] * inv;
        float var = fmaxf(rq[0] * inv - mean * mean, 0.f);
        float r = rsqrtf(var + 1e-5f);
        float sc = gamma[c] * r;
        g_scale[c] = sc;
        g_shift[c] = beta[c] - mean * sc;
    }
}

// ---------------- K4: apply BN (fp16 in, fp32 out), reverse + streaming ----
__global__ void bn_apply(float* __restrict__ out) {
    const size_t bi = (size_t)(gridDim.x - 1 - blockIdx.x);   // newest y first
    size_t i = bi * 256 + threadIdx.x;   // uint4 index (8 halves)
    const uint4 v = __ldcs((const uint4*)g_y + i);
    int c = (int)((i >> 11) & 127);
    float sc = g_scale[c], sh = g_shift[c];
    float2 f0 = __half22float2(*(const __half2*)&v.x);
    float2 f1 = __half22float2(*(const __half2*)&v.y);
    float2 f2 = __half22float2(*(const __half2*)&v.z);
    float2 f3 = __half22float2(*(const __half2*)&v.w);
    float4 o0, o1;
    o0.x = fmaf(f0.x, sc, sh); o0.y = fmaf(f0.y, sc, sh);
    o0.z = fmaf(f1.x, sc, sh); o0.w = fmaf(f1.y, sc, sh);
    o1.x = fmaf(f2.x, sc, sh); o1.y = fmaf(f2.y, sc, sh);
    o1.z = fmaf(f3.x, sc, sh); o1.w = fmaf(f3.y, sc, sh);
    __stcs((float4*)out + i * 2, o0);        // evict-first: protect y in L2
    __stcs((float4*)out + i * 2 + 1, o1);
}

extern "C" void kernel_launch(void* const* d_in, const int* in_sizes, int n_in,
                              void* d_out, int out_size) {
    const float* x     = (const float*)d_in[0];
    const float* w     = (const float*)d_in[1];
    const float* gamma = (const float*)d_in[2];
    const float* beta  = (const float*)d_in[3];
    float* out = (float*)d_out;

    static int nsm = 0;
    if (nsm == 0) {
        int dev = 0;
        cudaGetDevice(&dev);
        if (cudaDeviceGetAttribute(&nsm, cudaDevAttrMultiProcessorCount, dev)
                != cudaSuccess || nsm <= 0)
            nsm = 148;
    }

    cudaFuncSetAttribute(conv_kernel, cudaFuncAttributeMaxDynamicSharedMemorySize,
                         SMEM_TOTAL);

    lif_kernel<<<dim3(NB, HH, 4), 256>>>(x);
    wprep_kernel<<<(NW + 255) / 256, 256>>>(w);
    conv_kernel<<<nsm, 512, SMEM_TOTAL>>>(nsm);
    stats_final<<<NC2, 1024>>>(gamma, beta);
    bn_apply<<<NY / 8 / 256, 256>>>(out);
}

// round 16
// speedup vs baseline: 5.4409x; 1.0133x over previous
#include <cuda_runtime.h>
#include <cuda_fp16.h>
#include <cstdint>

// ---------------- problem dims ----------------
#define NT 4
#define NB 8
#define NC1 64
#define NC2 128
#define HH 128
#define WW 128
#define HW 16384
#define NIMG 32
#define NSPIKES 33554432       // NIMG*NC1*HW
#define NY 67108864            // NIMG*NC2*HW
#define NELEM_PER_CH 524288
#define NW 73728
#define NTILES 2048            // 32 images x 64 tiles (16x16 px)

// ---------------- conv smem layout ----------------
#define B_BYTES 147456         // 9 taps x 128 oc x 64 ch fp16, resident
#define HALO_BYTES 41472       // 324 rows (18x18) x 128 B
#define SMEM_TOTAL (B_BYTES + 2*HALO_BYTES)   // 230400

// ---------------- device scratch ----------------
__device__ __half g_spikes[NSPIKES];          // [n][y][x][c]  channel-last
__device__ __half g_y[NY];                    // [n][o][y][x]  fp16 intermediate
__device__ __half g_w[9*NC2*NC1];             // [kk][o][c] fp16 weights
__device__ float g_ps[NC2*NTILES];            // per-(ch,tile) sum
__device__ float g_pq[NC2*NTILES];            // per-(ch,tile) sumsq
__device__ float g_scale[NC2];
__device__ float g_shift[NC2];

// ---------------- helpers ----------------
__device__ __forceinline__ uint32_t smem_u32(const void* p) {
    uint32_t a;
    asm("{ .reg .u64 t; cvta.to.shared.u64 t, %1; cvt.u32.u64 %0, t; }"
        : "=r"(a) : "l"(p));
    return a;
}

__device__ __forceinline__ void mma_f16(float* d, const uint32_t* a,
                                        const uint32_t* b) {
    asm volatile(
        "mma.sync.aligned.m16n8k16.row.col.f32.f16.f16.f32 "
        "{%0,%1,%2,%3}, {%4,%5,%6,%7}, {%8,%9}, {%0,%1,%2,%3};"
        : "+f"(d[0]), "+f"(d[1]), "+f"(d[2]), "+f"(d[3])
        : "r"(a[0]), "r"(a[1]), "r"(a[2]), "r"(a[3]), "r"(b[0]), "r"(b[1]));
}

// ---------------- K1: LIF -> fp16 spikes, channel-last ----------------
__global__ void lif_kernel(const float* __restrict__ x) {
    __shared__ __half sbuf[128][24];   // 48B rows -> 16B-aligned uint4 reads
    const int b = blockIdx.x, y = blockIdx.y, cg = blockIdx.z;
    const int tid = threadIdx.x;
    const int c0 = cg * 16;
    const int wo = tid >> 1;
    const int co = (tid & 1) * 8;
    float mem[8], s[8];
#pragma unroll
    for (int j = 0; j < 8; j++) { mem[j] = 0.f; s[j] = 0.f; }
#pragma unroll
    for (int t = 0; t < NT; t++) {
        size_t xb = ((((size_t)t * NB + b) * NC1 + c0) * HH + y) * WW;
#pragma unroll
        for (int j = 0; j < 8; j++) {
            int idx = j * 256 + tid;
            int cl = idx >> 7, w = idx & 127;
            float xv = __ldcs(&x[xb + (size_t)cl * HW + w]);   // streaming
            mem[j] = (mem[j] - 0.5f * s[j]) * 0.25f + xv;
            s[j] = rintf(fminf(fmaxf(mem[j], 0.f), 1.f));
            sbuf[w][cl] = __float2half_rn(s[j]);   // {0,1} exact
        }
        __syncthreads();
        uint4 v = *(const uint4*)&sbuf[wo][co];
        size_t ob = (((size_t)(t * NB + b) * HH + y) * WW + wo) * NC1 + c0 + co;
        *(uint4*)(&g_spikes[ob]) = v;
        __syncthreads();
    }
}

// ---------------- K0: weights -> fp16, [kk][o][c] ----------------
__global__ void wprep_kernel(const float* __restrict__ w) {
    int i = blockIdx.x * 256 + threadIdx.x;
    if (i < NW) {
        int kx = i % 3, ky = (i / 3) % 3, c = (i / 9) % NC1, o = i / (NC1 * 9);
        g_w[((ky * 3 + kx) * NC2 + o) * NC1 + c] = __float2half_rn(w[i]);
    }
}

// ---------------- K2: persistent halo implicit-GEMM conv + fused stats ----
// grid = #SMs, 512 threads = 16 warps (4 px x 4 oc). Tile: 256 px x 128 oc.
// B (all 9 taps) resident in smem; per tile a single 18x18x64 halo load feeds
// all 36 MMA k-steps via per-lane-addressed ldmatrix (no per-tap barriers).
// B fragments fetched as x4 (both nn of a pair per instr).
__global__ void __launch_bounds__(512, 1) conv_kernel(int nsm) {
    extern __shared__ unsigned char smem[];
    const uint32_t sb = smem_u32(smem);
    const int tid = threadIdx.x;
    const int l = tid & 31, wid = tid >> 5;
    const int wm = wid & 3, wn = wid >> 2;

    // ---- A-side per-lane constants ----
    const int kcA = l >> 4;
    const int xl = ((l & 7) << 1) | ((l >> 3) & 1);   // permuted x of this lane's rows
    const int hm0 = (wm * 4) * 18 + xl;               // + m*18 + dk -> halo row
    // ---- B-side per-lane constants (x4 ldmatrix: lanes 16-31 -> +8 oc rows) ----
    const int rB4 = wn * 32 + (l & 7) + ((l >> 4) & 1) * 8;  // + pp*16
    const int kc4 = (l >> 3) & 1;
    const int l7 = l & 7;

    // ---- load resident B: 1152 rows x 128 B, swizzled by row&7 ----
#pragma unroll
    for (int j = 0; j < 18; j++) {
        int cid = tid + j * 512;          // 9216 chunks of 16 B
        int r = cid >> 3, cc = cid & 7;
        unsigned long long src = (unsigned long long)__cvta_generic_to_global(
            (void*)(g_w + (size_t)r * 64 + cc * 8));
        uint32_t dst = sb + (uint32_t)r * 128 + ((cc ^ (r & 7)) << 4);
        asm volatile("cp.async.cg.shared.global [%0], [%1], 16, 16;"
                     :: "r"(dst), "l"(src) : "memory");
    }

    auto issue_halo = [&](int t, int q) {
        const int n = t >> 6;
        const int gy0 = ((t >> 3) & 7) * 16 - 1;
        const int gx0 = (t & 7) * 16 - 1;
        const uint32_t hb = sb + B_BYTES + (uint32_t)q * HALO_BYTES;
#pragma unroll
        for (int j = 0; j < 6; j++) {
            int cid = tid + j * 512;      // 2592 chunks of 16 B
            if (cid < 2592) {
                int hr = cid >> 3, cc = cid & 7;
                int hy = hr / 18;
                int hx = hr - hy * 18;
                int gy = gy0 + hy, gx = gx0 + hx;
                bool ok = ((unsigned)gy < HH) && ((unsigned)gx < WW);
                int cgy = ok ? gy : 0, cgx = ok ? gx : 0;
                unsigned long long src =
                    (unsigned long long)__cvta_generic_to_global(
                        (void*)(g_spikes +
                                (((size_t)n * HH + cgy) * WW + cgx) * NC1 + cc * 8));
                uint32_t dst = hb + (uint32_t)hr * 128 +
                               ((cc ^ ((hr >> 1) & 7)) << 4);
                int sz = ok ? 16 : 0;
                asm volatile("cp.async.cg.shared.global [%0], [%1], 16, %2;"
                             :: "r"(dst), "l"(src), "r"(sz) : "memory");
            }
        }
        asm volatile("cp.async.commit_group;" ::: "memory");
    };

    int tile = blockIdx.x;
    issue_halo(tile, 0);   // commits B + halo0 as group 0
    int it = 0;
    float acc[4][4][4];

    while (tile < NTILES) {
        asm volatile("cp.async.wait_group 0;" ::: "memory");
        __syncthreads();                               // barrier 1: halo ready
        const int nxt = tile + nsm;
        if (nxt < NTILES) issue_halo(nxt, (it + 1) & 1);
        const uint32_t hs = sb + B_BYTES + (uint32_t)(it & 1) * HALO_BYTES;

#pragma unroll
        for (int m = 0; m < 4; m++)
#pragma unroll
            for (int nn = 0; nn < 4; nn++)
#pragma unroll
                for (int e = 0; e < 4; e++) acc[m][nn][e] = 0.f;

        // ---- 9 taps x 4 k-steps, no barriers, no waits ----
#pragma unroll 1
        for (int dy = 0; dy < 3; dy++) {
#pragma unroll
            for (int dx = 0; dx < 3; dx++) {
                const int dk = dy * 18 + dx;
                const uint32_t bB = sb + (uint32_t)(dy * 3 + dx) * 16384;
#pragma unroll
                for (int ks = 0; ks < 4; ks++) {
                    uint32_t bf[4][2];
#pragma unroll
                    for (int pp = 0; pp < 2; pp++) {
                        uint32_t off = (uint32_t)(rB4 + pp * 16) * 128 +
                                       (((ks * 2 + kc4) ^ l7) << 4);
                        asm volatile(
                            "ldmatrix.sync.aligned.m8n8.x4.shared.b16 "
                            "{%0,%1,%2,%3}, [%4];"
                            : "=r"(bf[pp * 2][0]), "=r"(bf[pp * 2][1]),
                              "=r"(bf[pp * 2 + 1][0]), "=r"(bf[pp * 2 + 1][1])
                            : "r"(bB + off));
                    }
#pragma unroll
                    for (int m = 0; m < 4; m++) {
                        const int hr = hm0 + m * 18 + dk;
                        uint32_t ad = hs + (uint32_t)hr * 128 +
                                      (((ks * 2 + kcA) ^ ((hr >> 1) & 7)) << 4);
                        uint32_t a[4];
                        asm volatile(
                            "ldmatrix.sync.aligned.m8n8.x4.shared.b16 "
                            "{%0,%1,%2,%3}, [%4];"
                            : "=r"(a[0]), "=r"(a[1]), "=r"(a[2]), "=r"(a[3])
                            : "r"(ad));
#pragma unroll
                        for (int nn = 0; nn < 4; nn++)
                            mma_f16(acc[m][nn], a, bf[nn]);
                    }
                }
            }
        }

        // ---- epilogue 1: packed fp16 y stores ----
        const int n = tile >> 6;
        const int ty0 = ((tile >> 3) & 7) * 16, tx0 = (tile & 7) * 16;
#pragma unroll
        for (int m = 0; m < 4; m++) {
            const int y = ty0 + wm * 4 + m;
            const int x = tx0 + ((l >> 2) << 1);
#pragma unroll
            for (int nn = 0; nn < 4; nn++) {
                const int oc = wn * 32 + nn * 8 + (l & 3) * 2;
                __half* p = g_y + ((size_t)n * NC2 + oc) * HW + y * WW + x;
                *(__half2*)p = __floats2half2_rn(acc[m][nn][0], acc[m][nn][2]);
                *(__half2*)(p + HW) = __floats2half2_rn(acc[m][nn][1], acc[m][nn][3]);
            }
        }

        __syncthreads();   // barrier 2: MMA reads of this halo stage done
        // ---- epilogue 2: fused BN partial stats (sred aliases dead stage) ----
        float* sred = (float*)(smem + B_BYTES + (size_t)(it & 1) * HALO_BYTES);
#pragma unroll
        for (int nn = 0; nn < 4; nn++) {
            float s0 = 0.f, s1 = 0.f, q0 = 0.f, q1 = 0.f;
#pragma unroll
            for (int m = 0; m < 4; m++) {
                float v0 = acc[m][nn][0], v1 = acc[m][nn][1];
                float v2 = acc[m][nn][2], v3 = acc[m][nn][3];
                s0 += v0 + v2; q0 += v0 * v0 + v2 * v2;
                s1 += v1 + v3; q1 += v1 * v1 + v3 * v3;
            }
#pragma unroll
            for (int o = 4; o <= 16; o <<= 1) {
                s0 += __shfl_xor_sync(0xffffffffu, s0, o);
                s1 += __shfl_xor_sync(0xffffffffu, s1, o);
                q0 += __shfl_xor_sync(0xffffffffu, q0, o);
                q1 += __shfl_xor_sync(0xffffffffu, q1, o);
            }
            if (l < 4) {
                float* p = sred + ((wid * 4 + nn) * 4 + l) * 4;
                p[0] = s0; p[1] = s1; p[2] = q0; p[3] = q1;
            }
        }
        __syncthreads();   // barrier 3
        if (tid < NC2) {
            const int c = tid;
            const int cwn = c >> 5, cnn = (c >> 3) & 3, csel = (c >> 1) & 3,
                      ccol = c & 1;
            float S = 0.f, Q = 0.f;
#pragma unroll
            for (int wm2 = 0; wm2 < 4; wm2++) {
                const float* p = sred + (((cwn * 4 + wm2) * 4 + cnn) * 4 + csel) * 4;
                S += p[ccol];
                Q += p[2 + ccol];
            }
            g_ps[c * NTILES + tile] = S;
            g_pq[c * NTILES + tile] = Q;
        }
        tile = nxt;
        it++;
    }
}

// ---------------- K3: finalize BN scale/shift ----------------
__global__ void stats_final(const float* __restrict__ gamma,
                            const float* __restrict__ beta) {
    const int c = blockIdx.x;
    const int tid = threadIdx.x;
    float s = 0.f, q = 0.f;
    for (int i = tid; i < NTILES; i += 1024) {
        s += g_ps[c * NTILES + i];
        q += g_pq[c * NTILES + i];
    }
    __shared__ float rs[1024], rq[1024];
    rs[tid] = s; rq[tid] = q;
    __syncthreads();
    for (int st = 512; st > 0; st >>= 1) {
        if (tid < st) { rs[tid] += rs[tid + st]; rq[tid] += rq[tid + st]; }
        __syncthreads();
    }
    if (tid == 0) {
        const float inv = 1.f / (float)NELEM_PER_CH;
        float mean = rs[0] * inv;
        float var = fmaxf(rq[0] * inv - mean * mean, 0.f);
        float r = rsqrtf(var + 1e-5f);
        float sc = gamma[c] * r;
        g_scale[c] = sc;
        g_shift[c] = beta[c] - mean * sc;
    }
}

// ---------------- K4: apply BN (fp16 in, fp32 out), reverse + streaming ----
__global__ void bn_apply(float* __restrict__ out) {
    const size_t bi = (size_t)(gridDim.x - 1 - blockIdx.x);   // newest y first
    size_t i = bi * 256 + threadIdx.x;   // uint4 index (8 halves)
    const uint4 v = __ldcs((const uint4*)g_y + i);
    int c = (int)((i >> 11) & 127);
    float sc = g_scale[c], sh = g_shift[c];
    float2 f0 = __half22float2(*(const __half2*)&v.x);
    float2 f1 = __half22float2(*(const __half2*)&v.y);
    float2 f2 = __half22float2(*(const __half2*)&v.z);
    float2 f3 = __half22float2(*(const __half2*)&v.w);
    float4 o0, o1;
    o0.x = fmaf(f0.x, sc, sh); o0.y = fmaf(f0.y, sc, sh);
    o0.z = fmaf(f1.x, sc, sh); o0.w = fmaf(f1.y, sc, sh);
    o1.x = fmaf(f2.x, sc, sh); o1.y = fmaf(f2.y, sc, sh);
    o1.z = fmaf(f3.x, sc, sh); o1.w = fmaf(f3.y, sc, sh);
    __stcs((float4*)out + i * 2, o0);        // evict-first: protect y in L2
    __stcs((float4*)out + i * 2 + 1, o1);
}

extern "C" void kernel_launch(void* const* d_in, const int* in_sizes, int n_in,
                              void* d_out, int out_size) {
    const float* x     = (const float*)d_in[0];
    const float* w     = (const float*)d_in[1];
    const float* gamma = (const float*)d_in[2];
    const float* beta  = (const float*)d_in[3];
    float* out = (float*)d_out;

    static int nsm = 0;
    if (nsm == 0) {
        int dev = 0;
        cudaGetDevice(&dev);
        if (cudaDeviceGetAttribute(&nsm, cudaDevAttrMultiProcessorCount, dev)
                != cudaSuccess || nsm <= 0)
            nsm = 148;
    }

    cudaFuncSetAttribute(conv_kernel, cudaFuncAttributeMaxDynamicSharedMemorySize,
                         SMEM_TOTAL);

    wprep_kernel<<<(NW + 255) / 256, 256>>>(w);
    lif_kernel<<<dim3(NB, HH, 4), 256>>>(x);
    conv_kernel<<<nsm, 512, SMEM_TOTAL>>>(nsm);
    stats_final<<<NC2, 1024>>>(gamma, beta);
    bn_apply<<<NY / 8 / 256, 256>>>(out);
}